// round 3
// baseline (speedup 1.0000x reference)
#include <cuda_runtime.h>
#include <cstdint>

// OnlineEmbedding: out[r, :] = table[ids[r], :]
//   ids:   [819200] int32, values in [0, 1e6)
//   table: [1e6, 64] float32 (row = 256 B = 16 float4)
//   out:   [819200, 64] float32
//
// R2 -> R3: 8 rows per 16-thread group (was 4).
//  - two int4 loads grab 8 ids
//  - 8 independent float4 gathers in flight per thread (MLP x8)
//  - still well under the ~55 outstanding-LDG/warp HW cap (9 per warp)
//  - __stcs output: evict-first write stream preserves L2 for table rows.

static constexpr int ROWS         = 4096 * 200;  // 819200
static constexpr int ROWS_PER_GRP = 8;
static constexpr int THR_PER_ROW  = 16;          // 16 * float4 = 64 floats
static constexpr int F4_PER_ROW   = 16;

__global__ __launch_bounds__(256)
void embed_gather_kernel(const int* __restrict__ ids,
                         const float4* __restrict__ table,
                         float4* __restrict__ out)
{
    int gtid = blockIdx.x * blockDim.x + threadIdx.x;
    int grp  = gtid >> 4;            // group of 16 threads
    int lane = gtid & 15;            // float4 index within row
    int row0 = grp * ROWS_PER_GRP;
    if (row0 >= ROWS) return;

    // 8 ids via two streamed vector loads (broadcast across the 16 lanes).
    int4 idA = __ldcs((const int4*)(ids + row0));
    int4 idB = __ldcs((const int4*)(ids + row0 + 4));

    // 8 independent gathers — all issued before any consumer.
    float4 v0 = __ldg(table + (size_t)idA.x * F4_PER_ROW + lane);
    float4 v1 = __ldg(table + (size_t)idA.y * F4_PER_ROW + lane);
    float4 v2 = __ldg(table + (size_t)idA.z * F4_PER_ROW + lane);
    float4 v3 = __ldg(table + (size_t)idA.w * F4_PER_ROW + lane);
    float4 v4 = __ldg(table + (size_t)idB.x * F4_PER_ROW + lane);
    float4 v5 = __ldg(table + (size_t)idB.y * F4_PER_ROW + lane);
    float4 v6 = __ldg(table + (size_t)idB.z * F4_PER_ROW + lane);
    float4 v7 = __ldg(table + (size_t)idB.w * F4_PER_ROW + lane);

    float4* o = out + (size_t)row0 * F4_PER_ROW + lane;
    __stcs(o + 0 * F4_PER_ROW, v0);
    __stcs(o + 1 * F4_PER_ROW, v1);
    __stcs(o + 2 * F4_PER_ROW, v2);
    __stcs(o + 3 * F4_PER_ROW, v3);
    __stcs(o + 4 * F4_PER_ROW, v4);
    __stcs(o + 5 * F4_PER_ROW, v5);
    __stcs(o + 6 * F4_PER_ROW, v6);
    __stcs(o + 7 * F4_PER_ROW, v7);
}

extern "C" void kernel_launch(void* const* d_in, const int* in_sizes, int n_in,
                              void* d_out, int out_size)
{
    const int*    ids   = (const int*)d_in[0];
    const float4* table = (const float4*)d_in[1];
    float4*       out   = (float4*)d_out;

    const int groups        = ROWS / ROWS_PER_GRP;          // 102400
    const int total_threads = groups * THR_PER_ROW;         // 1,638,400
    const int block = 256;
    const int grid  = (total_threads + block - 1) / block;  // 6400

    embed_gather_kernel<<<grid, block>>>(ids, table, out);
}